// round 12
// baseline (speedup 1.0000x reference)
#include <cuda_runtime.h>
#include <cstdint>

#define NS 21              // N_STIM + 1
#define PAIRS 441          // NS*NS
#define PAIRS_PAD 442      // pad so table bytes (442*8=3536) is a multiple of 16
#define TAB_BYTES (PAIRS_PAD * 8)
#define TPB 256
#define RPT 4              // rows per thread per chunk
#define RPB (TPB * RPT)    // 1024 rows per chunk
#define CHUNK_INTS (RPB * 5)
#define MAXGRID 592        // ~4 CTAs/SM on 148 SMs

__device__ alignas(16) float2 g_tab[PAIRS_PAD];   // {s, s*ln(s)} per (q,r) pair

// ---------------- kernel 1: compute the 441-entry pair table once ----------------
__global__ void precompute_kernel(const float* __restrict__ table,
                                  const float* __restrict__ w,
                                  const float* __restrict__ p_rho,
                                  const float* __restrict__ p_beta,
                                  const float* __restrict__ p_tau,
                                  const float* __restrict__ p_gamma)
{
    const int e = blockIdx.x * blockDim.x + threadIdx.x;
    if (e >= PAIRS) return;
    const float rho   = *p_rho;
    const float beta  = *p_beta;
    const float tau   = *p_tau;
    const float gamma = *p_gamma;
    const float w0 = w[0], w1 = w[1], w2 = w[2];

    const int q = e / NS, r = e % NS;
    const float dx = fabsf(table[q * 3 + 0] - table[r * 3 + 0]);
    const float dy = fabsf(table[q * 3 + 1] - table[r * 3 + 1]);
    const float dz = fabsf(table[q * 3 + 2] - table[r * 3 + 2]);

    float s;
    if (rho == 2.0f && tau == 1.0f) {
        const float acc = w0 * dx * dx + w1 * dy * dy + w2 * dz * dz;
        const float d   = sqrtf(acc);
        s = __expf(-beta * d) + gamma;
    } else {
        const float inv_rho = 1.0f / rho;
        const float acc = w0 * powf(dx, rho) + w1 * powf(dy, rho) + w2 * powf(dz, rho);
        const float d   = powf(acc, inv_rho);
        s = expf(-beta * powf(d, tau)) + gamma;
    }
    g_tab[e] = make_float2(s, s * __logf(s));
}

// ---------------- PTX helpers ----------------
__device__ __forceinline__ uint32_t smem_u32(const void* p) {
    uint32_t a;
    asm("{ .reg .u64 t; cvta.to.shared.u64 t, %1; cvt.u32.u64 %0, t; }"
        : "=r"(a) : "l"(p));
    return a;
}
__device__ __forceinline__ void mbar_init(uint32_t mb) {
    asm volatile("mbarrier.init.shared.b64 [%0], 1;" :: "r"(mb) : "memory");
}
__device__ __forceinline__ void mbar_expect(uint32_t mb, uint32_t tx) {
    asm volatile("mbarrier.arrive.expect_tx.shared.b64 _, [%0], %1;"
                 :: "r"(mb), "r"(tx) : "memory");
}
__device__ __forceinline__ void bulk_g2s(uint32_t dst, const void* src,
                                         uint32_t bytes, uint32_t mb) {
    asm volatile("cp.async.bulk.shared::cta.global.mbarrier::complete_tx::bytes "
                 "[%0], [%1], %2, [%3];"
                 :: "r"(dst), "l"(src), "r"(bytes), "r"(mb) : "memory");
}
__device__ __forceinline__ void mbar_wait(uint32_t mb, uint32_t parity) {
    uint32_t done;
    asm volatile("{\n\t.reg .pred p;\n\t"
                 "mbarrier.try_wait.parity.acquire.cta.shared::cta.b64 p, [%1], %2;\n\t"
                 "selp.b32 %0, 1, 0, p;\n\t}"
                 : "=r"(done) : "r"(mb), "r"(parity) : "memory");
    if (!done) {
        asm volatile("{\n\t.reg .pred P1;\n\t"
                     "W_%=:\n\t"
                     "mbarrier.try_wait.parity.acquire.cta.shared::cta.b64 P1, [%0], %1, 0x989680;\n\t"
                     "@P1 bra.uni D_%=;\n\t"
                     "bra.uni W_%=;\n\t"
                     "D_%=:\n\t}"
                     :: "r"(mb), "r"(parity) : "memory");
    }
}

// ---------------- kernel 2: persistent, double-buffered TMA pipeline ----------------
__global__ void __launch_bounds__(TPB, 4)
rank_rt_kernel(const int*   __restrict__ stim,    // [B,5]
               const float* __restrict__ p_upper,
               const float* __restrict__ p_mid,
               const float* __restrict__ p_rate,
               float* __restrict__ out,           // [B*4 rank | B rt]
               int B, int nChunks)
{
    __shared__ alignas(16) float2   sTab[PAIRS_PAD];
    __shared__ alignas(16) int      sIdx[2][CHUNK_INTS];
    __shared__ alignas(8)  uint64_t mbar[2];

    const int G = gridDim.x;
    const uint32_t mb[2] = { smem_u32(&mbar[0]), smem_u32(&mbar[1]) };

    if (threadIdx.x == 0) { mbar_init(mb[0]); mbar_init(mb[1]); }
    __syncthreads();

    const int c0 = blockIdx.x;
    if (c0 >= nChunks) return;

    // prologue: stage 0 = table + chunk c0 ; stage 1 = chunk c0+G
    if (threadIdx.x == 0) {
        const int r0 = min(RPB, B - c0 * RPB);
        const uint32_t b0 = (uint32_t)(r0 & ~3) * 20u;
        mbar_expect(mb[0], TAB_BYTES + b0);
        bulk_g2s(smem_u32(sTab), (const void*)g_tab, TAB_BYTES, mb[0]);
        if (b0) bulk_g2s(smem_u32(sIdx[0]), (const void*)(stim + (size_t)c0 * CHUNK_INTS), b0, mb[0]);

        const int c1 = c0 + G;
        if (c1 < nChunks) {
            const int r1 = min(RPB, B - c1 * RPB);
            const uint32_t b1 = (uint32_t)(r1 & ~3) * 20u;
            mbar_expect(mb[1], b1);
            if (b1) bulk_g2s(smem_u32(sIdx[1]), (const void*)(stim + (size_t)c1 * CHUNK_INTS), b1, mb[1]);
        }
    }

    const float upper = *p_upper;
    const float mid   = *p_mid;
    const float rate  = *p_rate;
    float* __restrict__ rt_out = out + (size_t)B * 4;

    int parity0 = 0, parity1 = 0;

    for (int i = 0, c = c0; c < nChunks; i++, c += G) {
        const int buf = i & 1;
        const uint32_t m = mb[buf];
        const int rows = min(RPB, B - c * RPB);

        // wait for this chunk's data
        if (buf == 0) { mbar_wait(m, parity0); parity0 ^= 1; }
        else          { mbar_wait(m, parity1); parity1 ^= 1; }

        // tail chunk only: scalar-fill remaining ints, zero-pad the rest
        if (rows < RPB) {
            const int bulkRows = rows & ~3;
            for (int k = bulkRows * 5 + threadIdx.x; k < CHUNK_INTS; k += TPB)
                sIdx[buf][k] = (k < rows * 5) ? stim[(size_t)c * CHUNK_INTS + k] : 0;
            __syncthreads();
        }

        // ---- batched 4-row compute ----
        const int row0 = c * RPB;
        const int* sb = sIdx[buf];

        int idx[RPT][5];
        #pragma unroll
        for (int h = 0; h < RPT; h++) {
            const int lrow = threadIdx.x + h * TPB;
            #pragma unroll
            for (int cc = 0; cc < 5; cc++)
                idx[h][cc] = sb[lrow * 5 + cc];    // stride-5: conflict-free
        }

        float2 e[RPT][4];
        #pragma unroll
        for (int h = 0; h < RPT; h++) {
            const int qb = idx[h][0] * NS;
            #pragma unroll
            for (int cc = 0; cc < 4; cc++)
                e[h][cc] = sTab[qb + idx[h][cc + 1]];
        }

        #pragma unroll
        for (int h = 0; h < RPT; h++) {
            const int row = row0 + threadIdx.x + h * TPB;
            if (row < B) {
                const float S  = (e[h][0].x + e[h][1].x) + (e[h][2].x + e[h][3].x);
                const float SL = (e[h][0].y + e[h][1].y) + (e[h][2].y + e[h][3].y);
                const float inv = __fdividef(1.0f, S);

                reinterpret_cast<float4*>(out)[row] =
                    make_float4(e[h][0].x * inv, e[h][1].x * inv,
                                e[h][2].x * inv, e[h][3].x * inv);

                const float H = __logf(S) - SL * inv;   // entropy
                rt_out[row] = upper * __fdividef(1.0f, 1.0f + __expf(-rate * (H - mid)));
            }
        }

        __syncthreads();   // all threads done reading sIdx[buf]

        // refill this buffer with chunk c + 2G (overlaps next chunk's compute)
        const int cn = c + 2 * G;
        if (threadIdx.x == 0 && cn < nChunks) {
            const int rn = min(RPB, B - cn * RPB);
            const uint32_t bn = (uint32_t)(rn & ~3) * 20u;
            mbar_expect(m, bn);
            if (bn) bulk_g2s(smem_u32(sIdx[buf]), (const void*)(stim + (size_t)cn * CHUNK_INTS), bn, m);
        }
    }
}

extern "C" void kernel_launch(void* const* d_in, const int* in_sizes, int n_in,
                              void* d_out, int out_size)
{
    const int*   stim    = (const int*)  d_in[0];
    const float* table   = (const float*)d_in[1];
    const float* w       = (const float*)d_in[2];
    const float* p_rho   = (const float*)d_in[3];
    const float* p_beta  = (const float*)d_in[4];
    const float* p_tau   = (const float*)d_in[5];
    const float* p_gamma = (const float*)d_in[6];
    const float* p_upper = (const float*)d_in[7];
    const float* p_mid   = (const float*)d_in[8];
    const float* p_rate  = (const float*)d_in[9];

    const int B = in_sizes[0] / 5;
    const int nChunks = (B + RPB - 1) / RPB;
    int grid = nChunks < MAXGRID ? nChunks : MAXGRID;
    if (grid < 1) grid = 1;

    precompute_kernel<<<2, 256>>>(table, w, p_rho, p_beta, p_tau, p_gamma);
    rank_rt_kernel<<<grid, TPB>>>(stim, p_upper, p_mid, p_rate,
                                  (float*)d_out, B, nChunks);
}

// round 13
// speedup vs baseline: 1.0807x; 1.0807x over previous
#include <cuda_runtime.h>
#include <cstdint>

#define NS 21              // N_STIM + 1
#define PAIRS 441          // NS*NS
#define PAIRS_PAD 442      // pad so table bytes (442*8=3536) is a multiple of 16
#define TAB_BYTES (PAIRS_PAD * 8)
#define TPB 512
#define RPT 4              // rows per thread
#define RPB (TPB * RPT)    // 2048 rows per block

__device__ alignas(16) float2 g_tab[PAIRS_PAD];   // {s, s*ln(s)} per (q,r) pair

// ---------------- kernel 1: compute the 441-entry pair table once ----------------
__global__ void precompute_kernel(const float* __restrict__ table,
                                  const float* __restrict__ w,
                                  const float* __restrict__ p_rho,
                                  const float* __restrict__ p_beta,
                                  const float* __restrict__ p_tau,
                                  const float* __restrict__ p_gamma)
{
    const int e = blockIdx.x * blockDim.x + threadIdx.x;
    if (e >= PAIRS) return;
    const float rho   = *p_rho;
    const float beta  = *p_beta;
    const float tau   = *p_tau;
    const float gamma = *p_gamma;
    const float w0 = w[0], w1 = w[1], w2 = w[2];

    const int q = e / NS, r = e % NS;
    const float dx = fabsf(table[q * 3 + 0] - table[r * 3 + 0]);
    const float dy = fabsf(table[q * 3 + 1] - table[r * 3 + 1]);
    const float dz = fabsf(table[q * 3 + 2] - table[r * 3 + 2]);

    float s;
    if (rho == 2.0f && tau == 1.0f) {
        // fast path for the actual parameterization: no powf
        const float acc = w0 * dx * dx + w1 * dy * dy + w2 * dz * dz;
        const float d   = sqrtf(acc);
        s = __expf(-beta * d) + gamma;
    } else {
        const float inv_rho = 1.0f / rho;
        const float acc = w0 * powf(dx, rho) + w1 * powf(dy, rho) + w2 * powf(dz, rho);
        const float d   = powf(acc, inv_rho);
        s = expf(-beta * powf(d, tau)) + gamma;
    }
    g_tab[e] = make_float2(s, s * __logf(s));
}

// ---------------- PTX helpers ----------------
__device__ __forceinline__ uint32_t smem_u32(const void* p) {
    uint32_t a;
    asm("{ .reg .u64 t; cvta.to.shared.u64 t, %1; cvt.u32.u64 %0, t; }"
        : "=r"(a) : "l"(p));
    return a;
}

// ---------------- kernel 2: main lookup kernel, TMA staged + 4-row batched ----------------
__global__ void __launch_bounds__(TPB)
rank_rt_kernel(const int*   __restrict__ stim,    // [B,5]
               const float* __restrict__ p_upper,
               const float* __restrict__ p_mid,
               const float* __restrict__ p_rate,
               float* __restrict__ out,           // [B*4 rank | B rt]
               int B)
{
    __shared__ alignas(16) float2   sTab[PAIRS_PAD];
    __shared__ alignas(16) int      sIdx[RPB * 5];
    __shared__ alignas(8)  uint64_t mbar;

    const int row0 = blockIdx.x * RPB;
    const int rows = min(RPB, B - row0);
    const int bulkRows  = rows & ~3;              // bulk size must be 16B multiple
    const uint32_t bulkBytes = (uint32_t)bulkRows * 20u;

    const uint32_t mbarA = smem_u32(&mbar);

    if (threadIdx.x == 0)
        asm volatile("mbarrier.init.shared.b64 [%0], 1;" :: "r"(mbarA) : "memory");
    __syncthreads();   // init visible to all threads before they wait

    if (threadIdx.x == 0) {
        const uint32_t tx = TAB_BYTES + bulkBytes;
        asm volatile("mbarrier.arrive.expect_tx.shared.b64 _, [%0], %1;"
                     :: "r"(mbarA), "r"(tx) : "memory");
        // table copy: 3536 B, global -> shared (async proxy, off the L1TEX path)
        asm volatile("cp.async.bulk.shared::cta.global.mbarrier::complete_tx::bytes "
                     "[%0], [%1], %2, [%3];"
                     :: "r"(smem_u32(sTab)), "l"((const void*)g_tab),
                        "r"((uint32_t)TAB_BYTES), "r"(mbarA) : "memory");
        // index block copy: bulkRows * 20 B (40KB for full blocks)
        if (bulkBytes > 0) {
            asm volatile("cp.async.bulk.shared::cta.global.mbarrier::complete_tx::bytes "
                         "[%0], [%1], %2, [%3];"
                         :: "r"(smem_u32(sIdx)), "l"((const void*)(stim + (size_t)row0 * 5)),
                            "r"(bulkBytes), "r"(mbarA) : "memory");
        }
    }

    // tail block only: scalar-fill remaining valid ints, zero the rest so
    // unguarded batched lookups stay in-bounds (index 0 is always safe)
    if (rows < RPB) {
        for (int k = bulkRows * 5 + threadIdx.x; k < RPB * 5; k += TPB)
            sIdx[k] = (k < rows * 5) ? stim[(size_t)row0 * 5 + k] : 0;
    }

    // wait for bulk copies (acquire orders subsequent LDS against TMA writes)
    {
        uint32_t done;
        asm volatile("{\n\t.reg .pred p;\n\t"
                     "mbarrier.try_wait.parity.acquire.cta.shared::cta.b64 p, [%1], 0;\n\t"
                     "selp.b32 %0, 1, 0, p;\n\t}"
                     : "=r"(done) : "r"(mbarA) : "memory");
        if (!done) {
            asm volatile("{\n\t.reg .pred P1;\n\t"
                         "W_%=:\n\t"
                         "mbarrier.try_wait.parity.acquire.cta.shared::cta.b64 P1, [%0], 0, 0x989680;\n\t"
                         "@P1 bra.uni D_%=;\n\t"
                         "bra.uni W_%=;\n\t"
                         "D_%=:\n\t}"
                         :: "r"(mbarA) : "memory");
        }
    }
    if (rows < RPB) __syncthreads();   // order scalar tail fills (uniform per block)

    const float upper = *p_upper;
    const float mid   = *p_mid;
    const float rate  = *p_rate;
    float* __restrict__ rt_out = out + (size_t)B * 4;

    // ---- explicit 4-row batch: all index loads, then all lookups, then math ----
    int idx[RPT][5];
    #pragma unroll
    for (int h = 0; h < RPT; h++) {
        const int lrow = threadIdx.x + h * TPB;
        #pragma unroll
        for (int c = 0; c < 5; c++)
            idx[h][c] = sIdx[lrow * 5 + c];        // stride-5: conflict-free
    }

    float2 e[RPT][4];
    #pragma unroll
    for (int h = 0; h < RPT; h++) {
        const int qb = idx[h][0] * NS;
        #pragma unroll
        for (int c = 0; c < 4; c++)
            e[h][c] = sTab[qb + idx[h][c + 1]];
    }

    #pragma unroll
    for (int h = 0; h < RPT; h++) {
        const int row = row0 + threadIdx.x + h * TPB;
        if (row < B) {
            const float S  = (e[h][0].x + e[h][1].x) + (e[h][2].x + e[h][3].x);
            const float SL = (e[h][0].y + e[h][1].y) + (e[h][2].y + e[h][3].y);
            const float inv = __fdividef(1.0f, S);

            reinterpret_cast<float4*>(out)[row] =
                make_float4(e[h][0].x * inv, e[h][1].x * inv,
                            e[h][2].x * inv, e[h][3].x * inv);

            const float H = __logf(S) - SL * inv;  // entropy
            rt_out[row] = upper * __fdividef(1.0f, 1.0f + __expf(-rate * (H - mid)));
        }
    }
}

extern "C" void kernel_launch(void* const* d_in, const int* in_sizes, int n_in,
                              void* d_out, int out_size)
{
    const int*   stim    = (const int*)  d_in[0];
    const float* table   = (const float*)d_in[1];
    const float* w       = (const float*)d_in[2];
    const float* p_rho   = (const float*)d_in[3];
    const float* p_beta  = (const float*)d_in[4];
    const float* p_tau   = (const float*)d_in[5];
    const float* p_gamma = (const float*)d_in[6];
    const float* p_upper = (const float*)d_in[7];
    const float* p_mid   = (const float*)d_in[8];
    const float* p_rate  = (const float*)d_in[9];

    const int B = in_sizes[0] / 5;
    int blocks = (B + RPB - 1) / RPB;
    if (blocks < 1) blocks = 1;

    precompute_kernel<<<2, 256>>>(table, w, p_rho, p_beta, p_tau, p_gamma);
    rank_rt_kernel<<<blocks, TPB>>>(stim, p_upper, p_mid, p_rate,
                                    (float*)d_out, B);
}

// round 14
// speedup vs baseline: 1.1056x; 1.0230x over previous
#include <cuda_runtime.h>
#include <cstdint>

#define NS 21              // N_STIM + 1
#define PAIRS 441          // NS*NS
#define PAIRS_PAD 442      // pad so table bytes (442*8=3536) is a multiple of 16
#define TAB_BYTES (PAIRS_PAD * 8)
#define TPB 256
#define RPT 2              // rows per thread
#define RPB (TPB * RPT)    // 512 rows per block

__device__ alignas(16) float2 g_tab[PAIRS_PAD];   // {s, s*ln(s)} per (q,r) pair

// ---------------- kernel 1: compute the 441-entry pair table once ----------------
__global__ void precompute_kernel(const float* __restrict__ table,
                                  const float* __restrict__ w,
                                  const float* __restrict__ p_rho,
                                  const float* __restrict__ p_beta,
                                  const float* __restrict__ p_tau,
                                  const float* __restrict__ p_gamma)
{
    const int e = blockIdx.x * blockDim.x + threadIdx.x;
    if (e >= PAIRS) return;
    const float rho   = *p_rho;
    const float beta  = *p_beta;
    const float tau   = *p_tau;
    const float gamma = *p_gamma;
    const float w0 = w[0], w1 = w[1], w2 = w[2];

    const int q = e / NS, r = e % NS;
    const float dx = fabsf(table[q * 3 + 0] - table[r * 3 + 0]);
    const float dy = fabsf(table[q * 3 + 1] - table[r * 3 + 1]);
    const float dz = fabsf(table[q * 3 + 2] - table[r * 3 + 2]);

    float s;
    if (rho == 2.0f && tau == 1.0f) {
        // fast path for the actual parameterization: no powf
        const float acc = w0 * dx * dx + w1 * dy * dy + w2 * dz * dz;
        const float d   = sqrtf(acc);
        s = __expf(-beta * d) + gamma;
    } else {
        const float inv_rho = 1.0f / rho;
        const float acc = w0 * powf(dx, rho) + w1 * powf(dy, rho) + w2 * powf(dz, rho);
        const float d   = powf(acc, inv_rho);
        s = expf(-beta * powf(d, tau)) + gamma;
    }
    g_tab[e] = make_float2(s, s * __logf(s));
}

// ---------------- PTX helpers ----------------
__device__ __forceinline__ uint32_t smem_u32(const void* p) {
    uint32_t a;
    asm("{ .reg .u64 t; cvta.to.shared.u64 t, %1; cvt.u32.u64 %0, t; }"
        : "=r"(a) : "l"(p));
    return a;
}

// ---------------- kernel 2: main lookup kernel, TMA staged + batched ----------------
__global__ void __launch_bounds__(TPB)
rank_rt_kernel(const int*   __restrict__ stim,    // [B,5]
               const float* __restrict__ p_upper,
               const float* __restrict__ p_mid,
               const float* __restrict__ p_rate,
               float* __restrict__ out,           // [B*4 rank | B rt]
               int B)
{
    __shared__ alignas(16) float2   sTab[PAIRS_PAD];
    __shared__ alignas(16) int      sIdx[RPB * 5];
    __shared__ alignas(8)  uint64_t mbar;

    const int row0 = blockIdx.x * RPB;
    const int rows = min(RPB, B - row0);
    const int bulkRows  = rows & ~3;              // bulk size must be 16B multiple
    const uint32_t bulkBytes = (uint32_t)bulkRows * 20u;

    const uint32_t mbarA = smem_u32(&mbar);

    if (threadIdx.x == 0)
        asm volatile("mbarrier.init.shared.b64 [%0], 1;" :: "r"(mbarA) : "memory");
    __syncthreads();   // init visible to all threads before they wait

    if (threadIdx.x == 0) {
        const uint32_t tx = TAB_BYTES + bulkBytes;
        asm volatile("mbarrier.arrive.expect_tx.shared.b64 _, [%0], %1;"
                     :: "r"(mbarA), "r"(tx) : "memory");
        // table copy: 3536 B, global -> shared (async proxy, off the L1TEX path)
        asm volatile("cp.async.bulk.shared::cta.global.mbarrier::complete_tx::bytes "
                     "[%0], [%1], %2, [%3];"
                     :: "r"(smem_u32(sTab)), "l"((const void*)g_tab),
                        "r"((uint32_t)TAB_BYTES), "r"(mbarA) : "memory");
        // index block copy: bulkRows * 20 B (10KB for full blocks)
        if (bulkBytes > 0) {
            asm volatile("cp.async.bulk.shared::cta.global.mbarrier::complete_tx::bytes "
                         "[%0], [%1], %2, [%3];"
                         :: "r"(smem_u32(sIdx)), "l"((const void*)(stim + (size_t)row0 * 5)),
                            "r"(bulkBytes), "r"(mbarA) : "memory");
        }
    }

    // hoisted scalar loads: L2 latency overlaps the TMA wait
    const float upper = *p_upper;
    const float mid   = *p_mid;
    const float rate  = *p_rate;

    // tail block only: scalar-fill remaining valid ints, zero the rest so
    // unguarded batched lookups stay in-bounds (index 0 is always safe)
    if (rows < RPB) {
        for (int k = bulkRows * 5 + threadIdx.x; k < RPB * 5; k += TPB)
            sIdx[k] = (k < rows * 5) ? stim[(size_t)row0 * 5 + k] : 0;
    }

    // wait for bulk copies (acquire orders subsequent LDS against TMA writes)
    {
        uint32_t done;
        asm volatile("{\n\t.reg .pred p;\n\t"
                     "mbarrier.try_wait.parity.acquire.cta.shared::cta.b64 p, [%1], 0;\n\t"
                     "selp.b32 %0, 1, 0, p;\n\t}"
                     : "=r"(done) : "r"(mbarA) : "memory");
        if (!done) {
            asm volatile("{\n\t.reg .pred P1;\n\t"
                         "W_%=:\n\t"
                         "mbarrier.try_wait.parity.acquire.cta.shared::cta.b64 P1, [%0], 0, 0x989680;\n\t"
                         "@P1 bra.uni D_%=;\n\t"
                         "bra.uni W_%=;\n\t"
                         "D_%=:\n\t}"
                         :: "r"(mbarA) : "memory");
        }
    }
    if (rows < RPB) __syncthreads();   // order scalar tail fills (uniform per block)

    float* __restrict__ rt_out = out + (size_t)B * 4;

    // ---- explicit 2-row batch: all index loads, then all lookups, then math ----
    int idx[RPT][5];
    #pragma unroll
    for (int h = 0; h < RPT; h++) {
        const int lrow = threadIdx.x + h * TPB;
        #pragma unroll
        for (int c = 0; c < 5; c++)
            idx[h][c] = sIdx[lrow * 5 + c];        // stride-5: conflict-free
    }

    float2 e[RPT][4];
    #pragma unroll
    for (int h = 0; h < RPT; h++) {
        const int qb = idx[h][0] * NS;
        #pragma unroll
        for (int c = 0; c < 4; c++)
            e[h][c] = sTab[qb + idx[h][c + 1]];
    }

    #pragma unroll
    for (int h = 0; h < RPT; h++) {
        const int row = row0 + threadIdx.x + h * TPB;
        if (row < B) {
            const float S  = (e[h][0].x + e[h][1].x) + (e[h][2].x + e[h][3].x);
            const float SL = (e[h][0].y + e[h][1].y) + (e[h][2].y + e[h][3].y);
            const float inv = __fdividef(1.0f, S);

            reinterpret_cast<float4*>(out)[row] =
                make_float4(e[h][0].x * inv, e[h][1].x * inv,
                            e[h][2].x * inv, e[h][3].x * inv);

            const float H = __logf(S) - SL * inv;  // entropy
            rt_out[row] = upper * __fdividef(1.0f, 1.0f + __expf(-rate * (H - mid)));
        }
    }
}

extern "C" void kernel_launch(void* const* d_in, const int* in_sizes, int n_in,
                              void* d_out, int out_size)
{
    const int*   stim    = (const int*)  d_in[0];
    const float* table   = (const float*)d_in[1];
    const float* w       = (const float*)d_in[2];
    const float* p_rho   = (const float*)d_in[3];
    const float* p_beta  = (const float*)d_in[4];
    const float* p_tau   = (const float*)d_in[5];
    const float* p_gamma = (const float*)d_in[6];
    const float* p_upper = (const float*)d_in[7];
    const float* p_mid   = (const float*)d_in[8];
    const float* p_rate  = (const float*)d_in[9];

    const int B = in_sizes[0] / 5;
    int blocks = (B + RPB - 1) / RPB;
    if (blocks < 1) blocks = 1;

    precompute_kernel<<<2, 256>>>(table, w, p_rho, p_beta, p_tau, p_gamma);
    rank_rt_kernel<<<blocks, TPB>>>(stim, p_upper, p_mid, p_rate,
                                    (float*)d_out, B);
}